// round 10
// baseline (speedup 1.0000x reference)
#include <cuda_runtime.h>
#include <cstdint>

// ---------------- problem constants ----------------
#define E_NUM     8
#define IN_F      2048
#define OUT_F     2048
#define TOTAL_T   16384
#define BM        128
#define BN        256
#define BK        32
#define KCH       (IN_F / BK)      // 64
#define NT_TILES  (OUT_F / BN)     // 8
#define MAXMT     136
#define NTH       256

#define A_SLOT_B   (1024 * 16)     // 1024 quads = 16 KB per A slot
#define B_STAGE_B  (2048 * 16)     // 2048 quads = 32 KB per B stage
#define SMEM_BYTES (2 * A_SLOT_B + 3 * B_STAGE_B)   // 131072

// ---------------- fragment-major W scratch ----------------
// [e*8+nt][kc][ks(4)][njp(4)][wn(4)][lane(32)] x uint4
__device__ static uint32_t g_Wr[(size_t)E_NUM * NT_TILES * KCH * BN * BK]; // 128 MB

// ---------------- ptx helpers (base ISA only) ------------
static __device__ __forceinline__ uint32_t smem_u32(const void* p) {
    uint32_t a;
    asm("{ .reg .u64 t; cvta.to.shared.u64 t, %1; cvt.u32.u64 %0, t; }" : "=r"(a) : "l"(p));
    return a;
}

static __device__ __forceinline__ uint32_t tf32_rna(float f) {
    uint32_t r;
    asm("cvt.rna.tf32.f32 %0, %1;" : "=r"(r) : "f"(f));
    return r;
}

static __device__ __forceinline__ void cp16(uint32_t dst, const void* src) {
    asm volatile("cp.async.cg.shared.global [%0], [%1], 16;"
                 :: "r"(dst), "l"(src) : "memory");
}

static __device__ __forceinline__ void cp_commit() {
    asm volatile("cp.async.commit_group;" ::: "memory");
}

static __device__ __forceinline__ void cp_wait1() {
    asm volatile("cp.async.wait_group 1;" ::: "memory");
}

static __device__ __forceinline__ void lds128(uint32_t* r, uint32_t addr) {
    asm volatile("ld.shared.v4.b32 {%0, %1, %2, %3}, [%4];"
                 : "=r"(r[0]), "=r"(r[1]), "=r"(r[2]), "=r"(r[3]) : "r"(addr));
}

static __device__ __forceinline__ void sts128(uint32_t addr, uint32_t x, uint32_t y,
                                              uint32_t z, uint32_t w) {
    asm volatile("st.shared.v4.b32 [%0], {%1, %2, %3, %4};"
                 :: "r"(addr), "r"(x), "r"(y), "r"(z), "r"(w) : "memory");
}

static __device__ __forceinline__ void mma8(float* c, const uint32_t* a, const uint32_t* b) {
    asm volatile(
        "mma.sync.aligned.m16n8k8.row.col.f32.tf32.tf32.f32 "
        "{%0,%1,%2,%3}, {%4,%5,%6,%7}, {%8,%9}, {%0,%1,%2,%3};"
        : "+f"(c[0]), "+f"(c[1]), "+f"(c[2]), "+f"(c[3])
        : "r"(a[0]), "r"(a[1]), "r"(a[2]), "r"(a[3]), "r"(b[0]), "r"(b[1]));
}

static __device__ __forceinline__ long long load_off(const int* p, int i, bool is64) {
    if (is64) return ((const long long*)p)[i];
    return (long long)p[i];
}

static __device__ __forceinline__ void tile_scan(const int* offs_raw, int mtile,
                                                 int& e, long long& row0, int& rows) {
    const bool is64 = ((offs_raw[1] | offs_raw[3] | offs_raw[5] | offs_raw[7]) == 0);
    e = -1; row0 = 0;
    long long rend = 0;
    int rem = mtile;
    long long lo = load_off(offs_raw, 0, is64);
    #pragma unroll
    for (int i = 0; i < E_NUM; i++) {
        long long hi = load_off(offs_raw, i + 1, is64);
        int t = (int)((hi - lo + (BM - 1)) >> 7);
        if (e < 0 && rem < t) { e = i; row0 = lo + ((long long)rem << 7); rend = hi; }
        if (e < 0) rem -= t;
        lo = hi;
    }
    rows = (e < 0) ? 0 : (int)(((rend - row0) < BM) ? (rend - row0) : BM);
}

// ---------------- pre-pass: pack W fragment-major (coalesced, quad-owning) ---
// grid (16, 64): x = 4-kc slice, y = e*8+nt. Thread owns whole quads.
__global__ void __launch_bounds__(256, 2)
pack_w_kernel(const float* __restrict__ W) {
    const int ent = blockIdx.y;
    const int nbase = (ent & 7) * BN;
    const float* We = W + (size_t)(ent >> 3) * OUT_F * IN_F;
    const int tid = threadIdx.x;
    const int ks  = tid & 3;
    const int rpb = tid >> 2;                  // 0..63

    #pragma unroll
    for (int kcL = 0; kcL < 4; kcL++) {
        const int kc = blockIdx.x * 4 + kcL;
        #pragma unroll
        for (int cell = 0; cell < 2; cell++) {
            const int rp  = rpb + 64 * cell;   // 0..127 row-pairs
            const int lnr = rp & 7;
            const int njp = (rp >> 3) & 3;
            const int wn  = rp >> 5;           // 0..3
            const int n   = nbase + wn * 64 + njp * 16 + lnr;
            const float* p0 = We + (size_t)n * IN_F + kc * BK + ks * 8;
            const float* p1 = p0 + 8 * IN_F;
            float4 r0a = __ldg((const float4*)p0);
            float4 r0b = __ldg((const float4*)(p0 + 4));
            float4 r1a = __ldg((const float4*)p1);
            float4 r1b = __ldg((const float4*)(p1 + 4));
            float a0[4] = {r0a.x, r0a.y, r0a.z, r0a.w};
            float a1[4] = {r0b.x, r0b.y, r0b.z, r0b.w};
            float a2[4] = {r1a.x, r1a.y, r1a.z, r1a.w};
            float a3[4] = {r1b.x, r1b.y, r1b.z, r1b.w};
            uint4* dst = (uint4*)g_Wr +
                ((size_t)ent * KCH + kc) * 2048 + (ks * 4 + njp) * 128 + wn * 32 + lnr * 4;
            #pragma unroll
            for (int j = 0; j < 4; j++) {
                uint4 o;
                o.x = tf32_rna(a0[j]);   // (n,   c)
                o.y = tf32_rna(a1[j]);   // (n,   c+4)
                o.z = tf32_rna(a2[j]);   // (n+8, c)
                o.w = tf32_rna(a3[j]);   // (n+8, c+4)
                dst[j] = o;
            }
        }
    }
}

// ---------------- main kernel: A packed in-kernel, consumer LDS.128 -> MMA ---
__global__ void __launch_bounds__(NTH, 1)
moe_mma_kernel(const float* __restrict__ X,
               const int*   __restrict__ offs_raw,
               const float* __restrict__ Bias,
               float*       __restrict__ Y)
{
    const int tid  = threadIdx.x;
    const int lane = tid & 31;
    const int wid  = tid >> 5;
    const int wm   = wid >> 2;   // 0..1
    const int wn   = wid & 3;    // 0..3
    const int n0   = blockIdx.x * BN;

    int e; long long row0; int rows;
    tile_scan(offs_raw, blockIdx.y, e, row0, rows);
    if (e < 0) return;

    extern __shared__ float smf[];
    const uint32_t smem_base = smem_u32(smf);
    const uint32_t b_base    = smem_base + 2 * A_SLOT_B;

    // ---- A producer: thread owns 4 quads of one (ks, row-pair) cell ----
    const int ksp = tid & 3;
    const int rp  = tid >> 2;                 // 0..63
    const int lrp = rp & 7;
    const int mip = (rp >> 3) & 3;
    const int wmp = rp >> 5;                  // 0..1
    const int r0p = wmp * 64 + mip * 16 + lrp;
    const bool v0 = r0p < rows;
    const bool v1 = (r0p + 8) < rows;
    const float* Xr0 = X + (size_t)(row0 + r0p) * IN_F + ksp * 8;
    const float* Xr1 = Xr0 + 8 * IN_F;
    // quad byte offsets: base + ((lrp*4+j) ^ ksp)*16 ; base = ((ksp*4+mip)*64 + wmp*32)*16
    const uint32_t aq_base = (uint32_t)(((ksp * 4 + mip) * 64 + wmp * 32) * 16);
    uint32_t aq_off[4];
    #pragma unroll
    for (int j = 0; j < 4; j++)
        aq_off[j] = aq_base + (uint32_t)(((lrp * 4 + j) ^ ksp) * 16);

    float sa0[4], sa1[4], sa2[4], sa3[4];     // raw A for next kc (16 regs)
    auto ldg_a = [&](int kc) {
        const size_t ko = (size_t)kc * BK;
        float4 z = make_float4(0.f, 0.f, 0.f, 0.f);
        float4 t0 = v0 ? __ldg((const float4*)(Xr0 + ko))     : z;
        float4 t1 = v0 ? __ldg((const float4*)(Xr0 + ko + 4)) : z;
        float4 t2 = v1 ? __ldg((const float4*)(Xr1 + ko))     : z;
        float4 t3 = v1 ? __ldg((const float4*)(Xr1 + ko + 4)) : z;
        sa0[0]=t0.x; sa0[1]=t0.y; sa0[2]=t0.z; sa0[3]=t0.w;
        sa1[0]=t1.x; sa1[1]=t1.y; sa1[2]=t1.z; sa1[3]=t1.w;
        sa2[0]=t2.x; sa2[1]=t2.y; sa2[2]=t2.z; sa2[3]=t2.w;
        sa3[0]=t3.x; sa3[1]=t3.y; sa3[2]=t3.z; sa3[3]=t3.w;
    };
    auto sts_a = [&](int slot) {
        const uint32_t ab = smem_base + (uint32_t)slot * A_SLOT_B;
        #pragma unroll
        for (int j = 0; j < 4; j++)
            sts128(ab + aq_off[j],
                   tf32_rna(sa0[j]), tf32_rna(sa2[j]),   // (r,c), (r+8,c)
                   tf32_rna(sa1[j]), tf32_rna(sa3[j]));  // (r,c+4), (r+8,c+4)
    };

    // ---- B producer: linear cp.async of pre-packed W ----
    const uint32_t* gB = g_Wr + ((size_t)e * NT_TILES + blockIdx.x) * KCH * (BN * BK);
    auto load_stage_b = [&](int kc, int sidx) {
        if (kc < KCH) {
            const uint32_t bb = b_base + (uint32_t)sidx * B_STAGE_B;
            const uint32_t* gb = gB + (size_t)kc * (BN * BK);
            #pragma unroll
            for (int j = 0; j < 8; j++)
                cp16(bb + (uint32_t)(tid + j * 256) * 16u, gb + (size_t)(tid + j * 256) * 4);
        }
        cp_commit();
    };

    // ---- accumulators ----
    float acc[4][8][4];
    #pragma unroll
    for (int mi = 0; mi < 4; mi++)
        #pragma unroll
        for (int nj = 0; nj < 8; nj++)
            #pragma unroll
            for (int q = 0; q < 4; q++) acc[mi][nj][q] = 0.0f;

    const uint32_t bbw = (uint32_t)(wn * 32 + lane) * 16u;

    // ---- prologue ----
    ldg_a(0);
    sts_a(0);
    ldg_a(1);
    load_stage_b(0, 0);
    load_stage_b(1, 1);

    uint32_t af[2][4][4], bq[2][4][4];

    int sidx = 0, pidx = 2;
    for (int kc = 0; kc < KCH; kc++) {
        cp_wait1();
        __syncthreads();
        load_stage_b(kc + 2, pidx);
        if (kc + 1 < KCH) sts_a((kc + 1) & 1);
        if (kc + 2 < KCH) ldg_a(kc + 2);

        const uint32_t As = smem_base + (uint32_t)(kc & 1) * A_SLOT_B;
        const uint32_t Bs = b_base + (uint32_t)sidx * B_STAGE_B;

        auto load_frags = [&](int ks, int bi) {
            #pragma unroll
            for (int mi = 0; mi < 4; mi++)
                lds128(af[bi][mi],
                       As + (uint32_t)((((ks * 4 + mi) * 64 + wm * 32) + (lane ^ ks)) * 16));
            #pragma unroll
            for (int njp = 0; njp < 4; njp++)
                lds128(bq[bi][njp], Bs + bbw + (uint32_t)(ks * 4 + njp) * 2048u);
        };

        load_frags(0, 0);
        #pragma unroll
        for (int ks = 0; ks < 4; ks++) {
            const int cur = ks & 1;
            if (ks < 3) load_frags(ks + 1, cur ^ 1);
            #pragma unroll
            for (int mi = 0; mi < 4; mi++) {
                #pragma unroll
                for (int njp = 0; njp < 4; njp++) {
                    mma8(acc[mi][2 * njp],     af[cur][mi], &bq[cur][njp][0]);
                    mma8(acc[mi][2 * njp + 1], af[cur][mi], &bq[cur][njp][2]);
                }
            }
        }

        sidx = (sidx == 2) ? 0 : sidx + 1;
        pidx = (pidx == 2) ? 0 : pidx + 1;
    }

    // ---- epilogue: bias add + float2 stores ----
    const int lr = lane >> 2;
    const int lc = lane & 3;
    #pragma unroll
    for (int nj = 0; nj < 8; nj++) {
        const int gc = n0 + wn * 64 + nj * 8 + lc * 2;
        const float b0 = __ldg(Bias + (size_t)e * OUT_F + gc);
        const float b1 = __ldg(Bias + (size_t)e * OUT_F + gc + 1);
        #pragma unroll
        for (int mi = 0; mi < 4; mi++) {
            const int gr = wm * 64 + mi * 16 + lr;
            if (gr < rows) {
                float2 v;
                v.x = acc[mi][nj][0] + b0;
                v.y = acc[mi][nj][1] + b1;
                *(float2*)(Y + (size_t)(row0 + gr) * OUT_F + gc) = v;
            }
            if (gr + 8 < rows) {
                float2 v;
                v.x = acc[mi][nj][2] + b0;
                v.y = acc[mi][nj][3] + b1;
                *(float2*)(Y + (size_t)(row0 + gr + 8) * OUT_F + gc) = v;
            }
        }
    }
}

extern "C" void kernel_launch(void* const* d_in, const int* in_sizes, int n_in,
                              void* d_out, int out_size) {
    const float* X    = (const float*)d_in[0];
    const int*   offs = (const int*)d_in[1];
    const float* W    = (const float*)d_in[2];
    const float* Bias = (const float*)d_in[3];
    float*       Y    = (float*)d_out;

    pack_w_kernel<<<dim3(16, E_NUM * NT_TILES), 256>>>(W);

    cudaFuncSetAttribute(moe_mma_kernel,
                         cudaFuncAttributeMaxDynamicSharedMemorySize, SMEM_BYTES);
    dim3 grid(NT_TILES, MAXMT);
    moe_mma_kernel<<<grid, NTH, SMEM_BYTES>>>(X, offs, Bias, Y);
}

// round 11
// speedup vs baseline: 1.0185x; 1.0185x over previous
#include <cuda_runtime.h>
#include <cstdint>

// ---------------- problem constants ----------------
#define E_NUM     8
#define IN_F      2048
#define OUT_F     2048
#define TOTAL_T   16384
#define BM        128
#define BN        256
#define BK        32
#define KCH       (IN_F / BK)      // 64
#define NT_TILES  (OUT_F / BN)     // 8
#define MAXMT     136
#define NTH       256
#define STAGES    3

#define A_FLOATS   (BM * BK)                   // 4096 (= 1024 quads)
#define B_FLOATS   (BN * BK)                   // 8192 (= 2048 quads)
#define STAGE_B    ((A_FLOATS + B_FLOATS) * 4) // 49152
#define SMEM_BYTES (STAGES * STAGE_B)          // 147456

// ---------------- fragment-major scratch ----------------
// X packed per m-tile:  [mtile][kc][ks(4)][mi(4)][wm(2)][lane(32)] x uint4
// W packed per n-tile:  [e*8+nt][kc][ks(4)][njp(4)][wn(4)][lane(32)] x uint4
__device__ static uint32_t g_Xr[(size_t)MAXMT * KCH * A_FLOATS];            // ~142.6 MB
__device__ static uint32_t g_Wr[(size_t)E_NUM * NT_TILES * KCH * B_FLOATS]; // 128 MB

// ---------------- ptx helpers (base ISA only) ------------
static __device__ __forceinline__ uint32_t smem_u32(const void* p) {
    uint32_t a;
    asm("{ .reg .u64 t; cvta.to.shared.u64 t, %1; cvt.u32.u64 %0, t; }" : "=r"(a) : "l"(p));
    return a;
}

static __device__ __forceinline__ uint32_t tf32_rna(float f) {
    uint32_t r;
    asm("cvt.rna.tf32.f32 %0, %1;" : "=r"(r) : "f"(f));
    return r;
}

static __device__ __forceinline__ void cp16(uint32_t dst, const void* src) {
    asm volatile("cp.async.cg.shared.global [%0], [%1], 16;"
                 :: "r"(dst), "l"(src) : "memory");
}

static __device__ __forceinline__ void cp_commit() {
    asm volatile("cp.async.commit_group;" ::: "memory");
}

static __device__ __forceinline__ void cp_wait1() {
    asm volatile("cp.async.wait_group 1;" ::: "memory");
}

static __device__ __forceinline__ void lds128(uint32_t* r, uint32_t addr) {
    asm volatile("ld.shared.v4.b32 {%0, %1, %2, %3}, [%4];"
                 : "=r"(r[0]), "=r"(r[1]), "=r"(r[2]), "=r"(r[3]) : "r"(addr));
}

static __device__ __forceinline__ void mma8(float* c, const uint32_t* a, const uint32_t* b) {
    asm volatile(
        "mma.sync.aligned.m16n8k8.row.col.f32.tf32.tf32.f32 "
        "{%0,%1,%2,%3}, {%4,%5,%6,%7}, {%8,%9}, {%0,%1,%2,%3};"
        : "+f"(c[0]), "+f"(c[1]), "+f"(c[2]), "+f"(c[3])
        : "r"(a[0]), "r"(a[1]), "r"(a[2]), "r"(a[3]), "r"(b[0]), "r"(b[1]));
}

static __device__ __forceinline__ long long load_off(const int* p, int i, bool is64) {
    if (is64) return ((const long long*)p)[i];
    return (long long)p[i];
}

static __device__ __forceinline__ void tile_scan(const int* offs_raw, int mtile,
                                                 int& e, long long& row0, int& rows) {
    const bool is64 = ((offs_raw[1] | offs_raw[3] | offs_raw[5] | offs_raw[7]) == 0);
    e = -1; row0 = 0;
    long long rend = 0;
    int rem = mtile;
    long long lo = load_off(offs_raw, 0, is64);
    #pragma unroll
    for (int i = 0; i < E_NUM; i++) {
        long long hi = load_off(offs_raw, i + 1, is64);
        int t = (int)((hi - lo + (BM - 1)) >> 7);
        if (e < 0 && rem < t) { e = i; row0 = lo + ((long long)rem << 7); rend = hi; }
        if (e < 0) rem -= t;
        lo = hi;
    }
    rows = (e < 0) ? 0 : (int)(((rend - row0) < BM) ? (rend - row0) : BM);
}

// ---------------- fused pre-pass: pack W and X fragment-major ----------------
// grid (16, 64 + MAXMT): y < 64 -> W block (ent = y), else X block (mtile = y-64).
// Thread owns 4 consecutive destination quads -> coalesced 64B stores.
__global__ void __launch_bounds__(256, 2)
pack_kernel(const float* __restrict__ X, const float* __restrict__ W,
            const int* __restrict__ offs_raw)
{
    const int tid = threadIdx.x;

    if (blockIdx.y < 64) {
        // ---------------- W part ----------------
        const int ent   = blockIdx.y;              // e*8 + nt
        const int nbase = (ent & 7) * BN;
        const float* We = W + (size_t)(ent >> 3) * OUT_F * IN_F;
        const int rp  = tid & 127;                 // 128 row-pairs
        const int ksh = tid >> 7;                  // 0..1
        const int lnr = rp & 7;
        const int wn  = (rp >> 3) & 3;
        const int njp = rp >> 5;
        const int n   = nbase + wn * 64 + njp * 16 + lnr;
        const float* Wn = We + (size_t)n * IN_F;

        #pragma unroll
        for (int kcL = 0; kcL < 4; kcL++) {
            const int kc = blockIdx.x * 4 + kcL;
            #pragma unroll
            for (int kss = 0; kss < 2; kss++) {
                const int ks = ksh * 2 + kss;
                const float* p0 = Wn + kc * BK + ks * 8;
                const float* p1 = p0 + 8 * IN_F;
                float4 t0 = __ldg((const float4*)p0);
                float4 t1 = __ldg((const float4*)(p0 + 4));
                float4 t2 = __ldg((const float4*)p1);
                float4 t3 = __ldg((const float4*)(p1 + 4));
                float a0[4] = {t0.x, t0.y, t0.z, t0.w};
                float a1[4] = {t1.x, t1.y, t1.z, t1.w};
                float a2[4] = {t2.x, t2.y, t2.z, t2.w};
                float a3[4] = {t3.x, t3.y, t3.z, t3.w};
                uint4* dst = (uint4*)g_Wr + ((size_t)ent * KCH + kc) * 2048
                           + (ks * 4 + njp) * 128 + wn * 32 + lnr * 4;
                #pragma unroll
                for (int j = 0; j < 4; j++) {
                    uint4 o;
                    o.x = tf32_rna(a0[j]);   // (n,   c)
                    o.y = tf32_rna(a1[j]);   // (n,   c+4)
                    o.z = tf32_rna(a2[j]);   // (n+8, c)
                    o.w = tf32_rna(a3[j]);   // (n+8, c+4)
                    dst[j] = o;
                }
            }
        }
    } else {
        // ---------------- X part ----------------
        const int mtile = blockIdx.y - 64;
        int e; long long row0; int rows;
        tile_scan(offs_raw, mtile, e, row0, rows);
        if (e < 0) return;

        const int ks  = tid >> 6;                  // 0..3
        const int rp  = tid & 63;                  // 64 row-pairs
        const int lrp = rp & 7;
        const int mi  = (rp >> 3) & 3;
        const int wm  = rp >> 5;                   // 0..1
        const int r   = wm * 64 + mi * 16 + lrp;
        const bool v0 = r < rows;
        const bool v1 = (r + 8) < rows;
        const float* Xr0 = X + (size_t)(row0 + r) * IN_F + ks * 8;
        const float* Xr1 = Xr0 + 8 * IN_F;
        uint4* dstb = (uint4*)g_Xr + (size_t)mtile * KCH * 1024
                    + ks * 256 + mi * 64 + wm * 32 + lrp * 4;

        #pragma unroll
        for (int kcL = 0; kcL < 4; kcL++) {
            const int kc = blockIdx.x * 4 + kcL;
            const float4 z = make_float4(0.f, 0.f, 0.f, 0.f);
            float4 t0 = v0 ? __ldg((const float4*)(Xr0 + kc * BK))     : z;
            float4 t1 = v0 ? __ldg((const float4*)(Xr0 + kc * BK + 4)) : z;
            float4 t2 = v1 ? __ldg((const float4*)(Xr1 + kc * BK))     : z;
            float4 t3 = v1 ? __ldg((const float4*)(Xr1 + kc * BK + 4)) : z;
            float a0[4] = {t0.x, t0.y, t0.z, t0.w};
            float a1[4] = {t1.x, t1.y, t1.z, t1.w};
            float a2[4] = {t2.x, t2.y, t2.z, t2.w};
            float a3[4] = {t3.x, t3.y, t3.z, t3.w};
            uint4* dst = dstb + (size_t)kc * 1024;
            #pragma unroll
            for (int j = 0; j < 4; j++) {
                uint4 o;
                o.x = tf32_rna(a0[j]);   // (r,   c)
                o.y = tf32_rna(a2[j]);   // (r+8, c)
                o.z = tf32_rna(a1[j]);   // (r,   c+4)
                o.w = tf32_rna(a3[j]);   // (r+8, c+4)
                dst[j] = o;
            }
        }
    }
}

// ---------------- main grouped-GEMM kernel: LDS.128 -> MMA (R9, unchanged) ---
__global__ void __launch_bounds__(NTH, 1)
moe_mma_kernel(const int*   __restrict__ offs_raw,
               const float* __restrict__ Bias,
               float*       __restrict__ Y)
{
    const int tid  = threadIdx.x;
    const int lane = tid & 31;
    const int wid  = tid >> 5;
    const int wm   = wid >> 2;   // 0..1
    const int wn   = wid & 3;    // 0..3
    const int n0   = blockIdx.x * BN;

    int e; long long row0; int rows;
    tile_scan(offs_raw, blockIdx.y, e, row0, rows);
    if (e < 0) return;

    extern __shared__ float smf[];
    const uint32_t smem_base = smem_u32(smf);

    const uint32_t* gA = g_Xr + (size_t)blockIdx.y * KCH * A_FLOATS;
    const uint32_t* gB = g_Wr + ((size_t)e * NT_TILES + blockIdx.x) * KCH * B_FLOATS;

    auto load_stage = [&](int kc, int sidx) {
        if (kc < KCH) {
            const uint32_t ab = smem_base + (uint32_t)sidx * STAGE_B;
            const uint32_t bb = ab + A_FLOATS * 4;
            const uint32_t* ga = gA + (size_t)kc * A_FLOATS;
            const uint32_t* gb = gB + (size_t)kc * B_FLOATS;
            #pragma unroll
            for (int j = 0; j < 4; j++)
                cp16(ab + (uint32_t)(tid + j * 256) * 16u, ga + (size_t)(tid + j * 256) * 4);
            #pragma unroll
            for (int j = 0; j < 8; j++)
                cp16(bb + (uint32_t)(tid + j * 256) * 16u, gb + (size_t)(tid + j * 256) * 4);
        }
        cp_commit();
    };

    float acc[4][8][4];
    #pragma unroll
    for (int mi = 0; mi < 4; mi++)
        #pragma unroll
        for (int nj = 0; nj < 8; nj++)
            #pragma unroll
            for (int q = 0; q < 4; q++) acc[mi][nj][q] = 0.0f;

    const uint32_t abw = (uint32_t)(wm * 32 + lane) * 16u;
    const uint32_t bbw = (uint32_t)(wn * 32 + lane) * 16u;

    load_stage(0, 0);
    load_stage(1, 1);

    uint32_t af[2][4][4], bq[2][4][4];

    int sidx = 0, pidx = 2;
    for (int kc = 0; kc < KCH; kc++) {
        cp_wait1();
        __syncthreads();
        load_stage(kc + 2, pidx);

        const uint32_t As = smem_base + (uint32_t)sidx * STAGE_B;
        const uint32_t Bs = As + A_FLOATS * 4;

        auto load_frags = [&](int ks, int bi) {
            #pragma unroll
            for (int mi = 0; mi < 4; mi++)
                lds128(af[bi][mi], As + abw + (uint32_t)(ks * 4 + mi) * 1024u);
            #pragma unroll
            for (int njp = 0; njp < 4; njp++)
                lds128(bq[bi][njp], Bs + bbw + (uint32_t)(ks * 4 + njp) * 2048u);
        };

        load_frags(0, 0);
        #pragma unroll
        for (int ks = 0; ks < 4; ks++) {
            const int cur = ks & 1;
            if (ks < 3) load_frags(ks + 1, cur ^ 1);
            #pragma unroll
            for (int mi = 0; mi < 4; mi++) {
                #pragma unroll
                for (int njp = 0; njp < 4; njp++) {
                    mma8(acc[mi][2 * njp],     af[cur][mi], &bq[cur][njp][0]);
                    mma8(acc[mi][2 * njp + 1], af[cur][mi], &bq[cur][njp][2]);
                }
            }
        }

        sidx = (sidx == STAGES - 1) ? 0 : sidx + 1;
        pidx = (pidx == STAGES - 1) ? 0 : pidx + 1;
    }

    // ---- epilogue: bias add + float2 stores ----
    const int lr = lane >> 2;
    const int lc = lane & 3;
    #pragma unroll
    for (int nj = 0; nj < 8; nj++) {
        const int gc = n0 + wn * 64 + nj * 8 + lc * 2;
        const float b0 = __ldg(Bias + (size_t)e * OUT_F + gc);
        const float b1 = __ldg(Bias + (size_t)e * OUT_F + gc + 1);
        #pragma unroll
        for (int mi = 0; mi < 4; mi++) {
            const int gr = wm * 64 + mi * 16 + lr;
            if (gr < rows) {
                float2 v;
                v.x = acc[mi][nj][0] + b0;
                v.y = acc[mi][nj][1] + b1;
                *(float2*)(Y + (size_t)(row0 + gr) * OUT_F + gc) = v;
            }
            if (gr + 8 < rows) {
                float2 v;
                v.x = acc[mi][nj][2] + b0;
                v.y = acc[mi][nj][3] + b1;
                *(float2*)(Y + (size_t)(row0 + gr + 8) * OUT_F + gc) = v;
            }
        }
    }
}

extern "C" void kernel_launch(void* const* d_in, const int* in_sizes, int n_in,
                              void* d_out, int out_size) {
    const float* X    = (const float*)d_in[0];
    const int*   offs = (const int*)d_in[1];
    const float* W    = (const float*)d_in[2];
    const float* Bias = (const float*)d_in[3];
    float*       Y    = (float*)d_out;

    pack_kernel<<<dim3(16, 64 + MAXMT), 256>>>(X, W, offs);

    cudaFuncSetAttribute(moe_mma_kernel,
                         cudaFuncAttributeMaxDynamicSharedMemorySize, SMEM_BYTES);
    dim3 grid(NT_TILES, MAXMT);
    moe_mma_kernel<<<grid, NTH, SMEM_BYTES>>>(offs, Bias, Y);
}

// round 16
// speedup vs baseline: 1.0960x; 1.0761x over previous
#include <cuda_runtime.h>
#include <cstdint>

// ---------------- problem constants ----------------
#define E_NUM     8
#define IN_F      2048
#define OUT_F     2048
#define TOTAL_T   16384
#define BM        128
#define BN        256
#define BK        32
#define KCH       (IN_F / BK)      // 64
#define NT_TILES  (OUT_F / BN)     // 8
#define MAXMT     136
#define NTH       256
#define STAGES    3

#define A_FLOATS   (BM * BK)                   // 4096 (= 1024 quads)
#define B_FLOATS   (BN * BK)                   // 8192 (= 2048 quads)
#define STAGE_B    ((A_FLOATS + B_FLOATS) * 4) // 49152
#define SMEM_BYTES (STAGES * STAGE_B)          // 147456

// ---------------- fragment-major scratch ----------------
__device__ static uint32_t g_Xr[(size_t)MAXMT * KCH * A_FLOATS];            // ~142.6 MB
__device__ static uint32_t g_Wr[(size_t)E_NUM * NT_TILES * KCH * B_FLOATS]; // 128 MB

// ---------------- ptx helpers (base ISA only) ------------
static __device__ __forceinline__ uint32_t smem_u32(const void* p) {
    uint32_t a;
    asm("{ .reg .u64 t; cvta.to.shared.u64 t, %1; cvt.u32.u64 %0, t; }" : "=r"(a) : "l"(p));
    return a;
}

static __device__ __forceinline__ uint32_t tf32_rna(float f) {
    uint32_t r;
    asm("cvt.rna.tf32.f32 %0, %1;" : "=r"(r) : "f"(f));
    return r;
}

static __device__ __forceinline__ void cp16(uint32_t dst, const void* src) {
    asm volatile("cp.async.cg.shared.global [%0], [%1], 16;"
                 :: "r"(dst), "l"(src) : "memory");
}

static __device__ __forceinline__ void cp_commit() {
    asm volatile("cp.async.commit_group;" ::: "memory");
}

static __device__ __forceinline__ void cp_wait1() {
    asm volatile("cp.async.wait_group 1;" ::: "memory");
}

static __device__ __forceinline__ void lds128(uint32_t* r, uint32_t addr) {
    asm volatile("ld.shared.v4.b32 {%0, %1, %2, %3}, [%4];"
                 : "=r"(r[0]), "=r"(r[1]), "=r"(r[2]), "=r"(r[3]) : "r"(addr));
}

static __device__ __forceinline__ void mma8(float* c, const uint32_t* a, const uint32_t* b) {
    asm volatile(
        "mma.sync.aligned.m16n8k8.row.col.f32.tf32.tf32.f32 "
        "{%0,%1,%2,%3}, {%4,%5,%6,%7}, {%8,%9}, {%0,%1,%2,%3};"
        : "+f"(c[0]), "+f"(c[1]), "+f"(c[2]), "+f"(c[3])
        : "r"(a[0]), "r"(a[1]), "r"(a[2]), "r"(a[3]), "r"(b[0]), "r"(b[1]));
}

static __device__ __forceinline__ long long load_off(const int* p, int i, bool is64) {
    if (is64) return ((const long long*)p)[i];
    return (long long)p[i];
}

static __device__ __forceinline__ void tile_scan(const int* offs_raw, int mtile,
                                                 int& e, long long& row0, int& rows) {
    const bool is64 = ((offs_raw[1] | offs_raw[3] | offs_raw[5] | offs_raw[7]) == 0);
    e = -1; row0 = 0;
    long long rend = 0;
    int rem = mtile;
    long long lo = load_off(offs_raw, 0, is64);
    #pragma unroll
    for (int i = 0; i < E_NUM; i++) {
        long long hi = load_off(offs_raw, i + 1, is64);
        int t = (int)((hi - lo + (BM - 1)) >> 7);
        if (e < 0 && rem < t) { e = i; row0 = lo + ((long long)rem << 7); rend = hi; }
        if (e < 0) rem -= t;
        lo = hi;
    }
    rows = (e < 0) ? 0 : (int)(((rend - row0) < BM) ? (rend - row0) : BM);
}

// ---------------- fused pre-pass: pack W and X fragment-major ----------------
__global__ void __launch_bounds__(256, 2)
pack_kernel(const float* __restrict__ X, const float* __restrict__ W,
            const int* __restrict__ offs_raw)
{
    const int tid = threadIdx.x;

    if (blockIdx.y < 64) {
        const int ent   = blockIdx.y;              // e*8 + nt
        const int nbase = (ent & 7) * BN;
        const float* We = W + (size_t)(ent >> 3) * OUT_F * IN_F;
        const int rp  = tid & 127;
        const int ksh = tid >> 7;
        const int lnr = rp & 7;
        const int wn  = (rp >> 3) & 3;
        const int njp = rp >> 5;
        const int n   = nbase + wn * 64 + njp * 16 + lnr;
        const float* Wn = We + (size_t)n * IN_F;

        #pragma unroll
        for (int kcL = 0; kcL < 4; kcL++) {
            const int kc = blockIdx.x * 4 + kcL;
            #pragma unroll
            for (int kss = 0; kss < 2; kss++) {
                const int ks = ksh * 2 + kss;
                const float* p0 = Wn + kc * BK + ks * 8;
                const float* p1 = p0 + 8 * IN_F;
                float4 t0 = __ldg((const float4*)p0);
                float4 t1 = __ldg((const float4*)(p0 + 4));
                float4 t2 = __ldg((const float4*)p1);
                float4 t3 = __ldg((const float4*)(p1 + 4));
                float a0[4] = {t0.x, t0.y, t0.z, t0.w};
                float a1[4] = {t1.x, t1.y, t1.z, t1.w};
                float a2[4] = {t2.x, t2.y, t2.z, t2.w};
                float a3[4] = {t3.x, t3.y, t3.z, t3.w};
                uint4* dst = (uint4*)g_Wr + ((size_t)ent * KCH + kc) * 2048
                           + (ks * 4 + njp) * 128 + wn * 32 + lnr * 4;
                #pragma unroll
                for (int j = 0; j < 4; j++) {
                    uint4 o;
                    o.x = tf32_rna(a0[j]);
                    o.y = tf32_rna(a1[j]);
                    o.z = tf32_rna(a2[j]);
                    o.w = tf32_rna(a3[j]);
                    dst[j] = o;
                }
            }
        }
    } else {
        const int mtile = blockIdx.y - 64;
        int e; long long row0; int rows;
        tile_scan(offs_raw, mtile, e, row0, rows);
        if (e < 0) return;

        const int ks  = tid >> 6;
        const int rp  = tid & 63;
        const int lrp = rp & 7;
        const int mi  = (rp >> 3) & 3;
        const int wm  = rp >> 5;
        const int r   = wm * 64 + mi * 16 + lrp;
        const bool v0 = r < rows;
        const bool v1 = (r + 8) < rows;
        const float* Xr0 = X + (size_t)(row0 + r) * IN_F + ks * 8;
        const float* Xr1 = Xr0 + 8 * IN_F;
        uint4* dstb = (uint4*)g_Xr + (size_t)mtile * KCH * 1024
                    + ks * 256 + mi * 64 + wm * 32 + lrp * 4;

        #pragma unroll
        for (int kcL = 0; kcL < 4; kcL++) {
            const int kc = blockIdx.x * 4 + kcL;
            const float4 z = make_float4(0.f, 0.f, 0.f, 0.f);
            float4 t0 = v0 ? __ldg((const float4*)(Xr0 + kc * BK))     : z;
            float4 t1 = v0 ? __ldg((const float4*)(Xr0 + kc * BK + 4)) : z;
            float4 t2 = v1 ? __ldg((const float4*)(Xr1 + kc * BK))     : z;
            float4 t3 = v1 ? __ldg((const float4*)(Xr1 + kc * BK + 4)) : z;
            float a0[4] = {t0.x, t0.y, t0.z, t0.w};
            float a1[4] = {t1.x, t1.y, t1.z, t1.w};
            float a2[4] = {t2.x, t2.y, t2.z, t2.w};
            float a3[4] = {t3.x, t3.y, t3.z, t3.w};
            uint4* dst = dstb + (size_t)kc * 1024;
            #pragma unroll
            for (int j = 0; j < 4; j++) {
                uint4 o;
                o.x = tf32_rna(a0[j]);
                o.y = tf32_rna(a2[j]);
                o.z = tf32_rna(a1[j]);
                o.w = tf32_rna(a3[j]);
                dst[j] = o;
            }
        }
    }
}

// ---------- main kernel: LDS.128 -> MMA, cp.async issues interleaved ---------
__global__ void __launch_bounds__(NTH, 1)
moe_mma_kernel(const int*   __restrict__ offs_raw,
               const float* __restrict__ Bias,
               float*       __restrict__ Y)
{
    const int tid  = threadIdx.x;
    const int lane = tid & 31;
    const int wid  = tid >> 5;
    const int wm   = wid >> 2;   // 0..1
    const int wn   = wid & 3;    // 0..3
    const int n0   = blockIdx.x * BN;

    int e; long long row0; int rows;
    tile_scan(offs_raw, blockIdx.y, e, row0, rows);
    if (e < 0) return;

    extern __shared__ float smf[];
    const uint32_t smem_base = smem_u32(smf);

    const uint32_t* gA = g_Xr + (size_t)blockIdx.y * KCH * A_FLOATS;
    const uint32_t* gB = g_Wr + ((size_t)e * NT_TILES + blockIdx.x) * KCH * B_FLOATS;

    // prologue-only burst loader (used twice before the mainloop)
    auto load_stage_burst = [&](int kc, int sidx) {
        const uint32_t ab = smem_base + (uint32_t)sidx * STAGE_B;
        const uint32_t bb = ab + A_FLOATS * 4;
        const uint32_t* ga = gA + (size_t)kc * A_FLOATS;
        const uint32_t* gb = gB + (size_t)kc * B_FLOATS;
        #pragma unroll
        for (int j = 0; j < 4; j++)
            cp16(ab + (uint32_t)(tid + j * 256) * 16u, ga + (size_t)(tid + j * 256) * 4);
        #pragma unroll
        for (int j = 0; j < 8; j++)
            cp16(bb + (uint32_t)(tid + j * 256) * 16u, gb + (size_t)(tid + j * 256) * 4);
        cp_commit();
    };

    float acc[4][8][4];
    #pragma unroll
    for (int mi = 0; mi < 4; mi++)
        #pragma unroll
        for (int nj = 0; nj < 8; nj++)
            #pragma unroll
            for (int q = 0; q < 4; q++) acc[mi][nj][q] = 0.0f;

    const uint32_t abw = (uint32_t)(wm * 32 + lane) * 16u;
    const uint32_t bbw = (uint32_t)(wn * 32 + lane) * 16u;

    load_stage_burst(0, 0);
    load_stage_burst(1, 1);

    uint32_t af[2][4][4], bq[2][4][4];

    int sidx = 0, pidx = 2;
    for (int kc = 0; kc < KCH; kc++) {
        cp_wait1();
        __syncthreads();

        const uint32_t As = smem_base + (uint32_t)sidx * STAGE_B;
        const uint32_t Bs = As + A_FLOATS * 4;

        auto load_frags = [&](int ks, int bi) {
            #pragma unroll
            for (int mi = 0; mi < 4; mi++)
                lds128(af[bi][mi], As + abw + (uint32_t)(ks * 4 + mi) * 1024u);
            #pragma unroll
            for (int njp = 0; njp < 4; njp++)
                lds128(bq[bi][njp], Bs + bbw + (uint32_t)(ks * 4 + njp) * 2048u);
        };

        // consumer work FIRST: get the tensor pipe fed before any producer issue
        load_frags(0, 0);

        // prefetch-target pointers for stage kc+2 (issued 3 cp16 per ks below)
        const bool pf = (kc + 2) < KCH;
        const uint32_t ab = smem_base + (uint32_t)pidx * STAGE_B;
        const uint32_t bb = ab + A_FLOATS * 4;
        const uint32_t* ga = gA + (size_t)(kc + 2) * A_FLOATS;
        const uint32_t* gb = gB + (size_t)(kc + 2) * B_FLOATS;

        #pragma unroll
        for (int ks = 0; ks < 4; ks++) {
            const int cur = ks & 1;
            if (ks < 3) load_frags(ks + 1, cur ^ 1);

            if (pf) {
                #pragma unroll
                for (int j = 3 * ks; j < 3 * ks + 3; j++) {
                    const uint32_t q = (uint32_t)(tid + j * 256);
                    if (j < 4) cp16(ab + q * 16u, ga + (size_t)q * 4);
                    else {
                        const uint32_t qb = (uint32_t)(tid + (j - 4) * 256);
                        cp16(bb + qb * 16u, gb + (size_t)qb * 4);
                    }
                }
            }

            #pragma unroll
            for (int mi = 0; mi < 4; mi++) {
                #pragma unroll
                for (int njp = 0; njp < 4; njp++) {
                    mma8(acc[mi][2 * njp],     af[cur][mi], &bq[cur][njp][0]);
                    mma8(acc[mi][2 * njp + 1], af[cur][mi], &bq[cur][njp][2]);
                }
            }
        }
        cp_commit();   // exactly one commit per kc -> wait1 semantics unchanged

        sidx = (sidx == STAGES - 1) ? 0 : sidx + 1;
        pidx = (pidx == STAGES - 1) ? 0 : pidx + 1;
    }

    // ---- epilogue: bias add + float2 stores ----
    const int lr = lane >> 2;
    const int lc = lane & 3;
    #pragma unroll
    for (int nj = 0; nj < 8; nj++) {
        const int gc = n0 + wn * 64 + nj * 8 + lc * 2;
        const float b0 = __ldg(Bias + (size_t)e * OUT_F + gc);
        const float b1 = __ldg(Bias + (size_t)e * OUT_F + gc + 1);
        #pragma unroll
        for (int mi = 0; mi < 4; mi++) {
            const int gr = wm * 64 + mi * 16 + lr;
            if (gr < rows) {
                float2 v;
                v.x = acc[mi][nj][0] + b0;
                v.y = acc[mi][nj][1] + b1;
                *(float2*)(Y + (size_t)(row0 + gr) * OUT_F + gc) = v;
            }
            if (gr + 8 < rows) {
                float2 v;
                v.x = acc[mi][nj][2] + b0;
                v.y = acc[mi][nj][3] + b1;
                *(float2*)(Y + (size_t)(row0 + gr + 8) * OUT_F + gc) = v;
            }
        }
    }
}

extern "C" void kernel_launch(void* const* d_in, const int* in_sizes, int n_in,
                              void* d_out, int out_size) {
    const float* X    = (const float*)d_in[0];
    const int*   offs = (const int*)d_in[1];
    const float* W    = (const float*)d_in[2];
    const float* Bias = (const float*)d_in[3];
    float*       Y    = (float*)d_out;

    pack_kernel<<<dim3(16, 64 + MAXMT), 256>>>(X, W, offs);

    cudaFuncSetAttribute(moe_mma_kernel,
                         cudaFuncAttributeMaxDynamicSharedMemorySize, SMEM_BYTES);
    dim3 grid(NT_TILES, MAXMT);
    moe_mma_kernel<<<grid, NTH, SMEM_BYTES>>>(offs, Bias, Y);
}

// round 17
// speedup vs baseline: 1.1516x; 1.0507x over previous
#include <cuda_runtime.h>
#include <cstdint>

// ---------------- problem constants ----------------
#define E_NUM     8
#define IN_F      2048
#define OUT_F     2048
#define TOTAL_T   16384
#define BM        128
#define BN        128
#define BK        32
#define KCH       (IN_F / BK)      // 64
#define NT_TILES  (OUT_F / BN)     // 16
#define MAXMT     136
#define NTH       128              // 4 warps, 2x2 grid of 64x64 warp tiles
#define STAGES    3

#define A_FLOATS   (BM * BK)                   // 4096 (= 1024 quads)
#define B_FLOATS   (BN * BK)                   // 4096 (= 1024 quads)
#define STAGE_B    ((A_FLOATS + B_FLOATS) * 4) // 32768
#define SMEM_BYTES (STAGES * STAGE_B)          // 98304 -> 2 CTAs/SM

// ---------------- fragment-major scratch ----------------
// X per m-tile: [mtile][kc][ks(4)][mi(4)][wm(2)][lane(32)] x uint4
// W per n-tile: [e*16+nt][kc][ks(4)][njp(4)][wn(2)][lane(32)] x uint4
__device__ static uint32_t g_Xr[(size_t)MAXMT * KCH * A_FLOATS];              // ~142.6 MB
__device__ static uint32_t g_Wr[(size_t)E_NUM * NT_TILES * KCH * B_FLOATS];   // 128 MB

// ---------------- ptx helpers (base ISA only) ------------
static __device__ __forceinline__ uint32_t smem_u32(const void* p) {
    uint32_t a;
    asm("{ .reg .u64 t; cvta.to.shared.u64 t, %1; cvt.u32.u64 %0, t; }" : "=r"(a) : "l"(p));
    return a;
}

static __device__ __forceinline__ uint32_t tf32_rna(float f) {
    uint32_t r;
    asm("cvt.rna.tf32.f32 %0, %1;" : "=r"(r) : "f"(f));
    return r;
}

static __device__ __forceinline__ void cp16(uint32_t dst, const void* src) {
    asm volatile("cp.async.cg.shared.global [%0], [%1], 16;"
                 :: "r"(dst), "l"(src) : "memory");
}

static __device__ __forceinline__ void cp_commit() {
    asm volatile("cp.async.commit_group;" ::: "memory");
}

static __device__ __forceinline__ void cp_wait1() {
    asm volatile("cp.async.wait_group 1;" ::: "memory");
}

static __device__ __forceinline__ void lds128(uint32_t* r, uint32_t addr) {
    asm volatile("ld.shared.v4.b32 {%0, %1, %2, %3}, [%4];"
                 : "=r"(r[0]), "=r"(r[1]), "=r"(r[2]), "=r"(r[3]) : "r"(addr));
}

static __device__ __forceinline__ void mma8(float* c, const uint32_t* a, const uint32_t* b) {
    asm volatile(
        "mma.sync.aligned.m16n8k8.row.col.f32.tf32.tf32.f32 "
        "{%0,%1,%2,%3}, {%4,%5,%6,%7}, {%8,%9}, {%0,%1,%2,%3};"
        : "+f"(c[0]), "+f"(c[1]), "+f"(c[2]), "+f"(c[3])
        : "r"(a[0]), "r"(a[1]), "r"(a[2]), "r"(a[3]), "r"(b[0]), "r"(b[1]));
}

static __device__ __forceinline__ long long load_off(const int* p, int i, bool is64) {
    if (is64) return ((const long long*)p)[i];
    return (long long)p[i];
}

static __device__ __forceinline__ void tile_scan(const int* offs_raw, int mtile,
                                                 int& e, long long& row0, int& rows) {
    const bool is64 = ((offs_raw[1] | offs_raw[3] | offs_raw[5] | offs_raw[7]) == 0);
    e = -1; row0 = 0;
    long long rend = 0;
    int rem = mtile;
    long long lo = load_off(offs_raw, 0, is64);
    #pragma unroll
    for (int i = 0; i < E_NUM; i++) {
        long long hi = load_off(offs_raw, i + 1, is64);
        int t = (int)((hi - lo + (BM - 1)) >> 7);
        if (e < 0 && rem < t) { e = i; row0 = lo + ((long long)rem << 7); rend = hi; }
        if (e < 0) rem -= t;
        lo = hi;
    }
    rows = (e < 0) ? 0 : (int)(((rend - row0) < BM) ? (rend - row0) : BM);
}

// ---------------- fused pre-pass: pack W and X fragment-major ----------------
// grid (16, 128 + MAXMT): y < 128 -> W block (ent = y), else X block (mtile = y-128).
__global__ void __launch_bounds__(256, 2)
pack_kernel(const float* __restrict__ X, const float* __restrict__ W,
            const int* __restrict__ offs_raw)
{
    const int tid = threadIdx.x;

    if (blockIdx.y < 128) {
        // ---------------- W part: one (expert, 128-col n-tile) block ----------
        const int ent   = blockIdx.y;               // e*16 + nt
        const int nbase = (ent & 15) * BN;
        const float* We = W + (size_t)(ent >> 4) * OUT_F * IN_F;
        const int ks  = tid >> 6;                   // 0..3
        const int rp  = tid & 63;                   // 64 row-pairs
        const int lnr = rp & 7;
        const int wn  = (rp >> 3) & 1;
        const int njp = rp >> 4;                    // 0..3
        const int n   = nbase + wn * 64 + njp * 16 + lnr;
        const float* Wn = We + (size_t)n * IN_F + ks * 8;
        uint4* dstb = (uint4*)g_Wr + (size_t)ent * KCH * 1024
                    + ks * 256 + njp * 64 + wn * 32 + lnr * 4;

        #pragma unroll
        for (int kcL = 0; kcL < 4; kcL++) {
            const int kc = blockIdx.x * 4 + kcL;
            const float* p0 = Wn + kc * BK;
            const float* p1 = p0 + 8 * IN_F;
            float4 t0 = __ldg((const float4*)p0);
            float4 t1 = __ldg((const float4*)(p0 + 4));
            float4 t2 = __ldg((const float4*)p1);
            float4 t3 = __ldg((const float4*)(p1 + 4));
            float a0[4] = {t0.x, t0.y, t0.z, t0.w};
            float a1[4] = {t1.x, t1.y, t1.z, t1.w};
            float a2[4] = {t2.x, t2.y, t2.z, t2.w};
            float a3[4] = {t3.x, t3.y, t3.z, t3.w};
            uint4* dst = dstb + (size_t)kc * 1024;
            #pragma unroll
            for (int j = 0; j < 4; j++) {
                uint4 o;
                o.x = tf32_rna(a0[j]);   // (n,   c)
                o.y = tf32_rna(a1[j]);   // (n,   c+4)
                o.z = tf32_rna(a2[j]);   // (n+8, c)
                o.w = tf32_rna(a3[j]);   // (n+8, c+4)
                dst[j] = o;
            }
        }
    } else {
        // ---------------- X part: one 128-row m-tile ----------
        const int mtile = blockIdx.y - 128;
        int e; long long row0; int rows;
        tile_scan(offs_raw, mtile, e, row0, rows);
        if (e < 0) return;

        const int ks  = tid >> 6;                   // 0..3
        const int rp  = tid & 63;                   // 64 row-pairs
        const int lrp = rp & 7;
        const int mi  = (rp >> 3) & 3;
        const int wm  = rp >> 5;                    // 0..1
        const int r   = wm * 64 + mi * 16 + lrp;
        const bool v0 = r < rows;
        const bool v1 = (r + 8) < rows;
        const float* Xr0 = X + (size_t)(row0 + r) * IN_F + ks * 8;
        const float* Xr1 = Xr0 + 8 * IN_F;
        uint4* dstb = (uint4*)g_Xr + (size_t)mtile * KCH * 1024
                    + ks * 256 + mi * 64 + wm * 32 + lrp * 4;

        #pragma unroll
        for (int kcL = 0; kcL < 4; kcL++) {
            const int kc = blockIdx.x * 4 + kcL;
            const float4 z = make_float4(0.f, 0.f, 0.f, 0.f);
            float4 t0 = v0 ? __ldg((const float4*)(Xr0 + kc * BK))     : z;
            float4 t1 = v0 ? __ldg((const float4*)(Xr0 + kc * BK + 4)) : z;
            float4 t2 = v1 ? __ldg((const float4*)(Xr1 + kc * BK))     : z;
            float4 t3 = v1 ? __ldg((const float4*)(Xr1 + kc * BK + 4)) : z;
            float a0[4] = {t0.x, t0.y, t0.z, t0.w};
            float a1[4] = {t1.x, t1.y, t1.z, t1.w};
            float a2[4] = {t2.x, t2.y, t2.z, t2.w};
            float a3[4] = {t3.x, t3.y, t3.z, t3.w};
            uint4* dst = dstb + (size_t)kc * 1024;
            #pragma unroll
            for (int j = 0; j < 4; j++) {
                uint4 o;
                o.x = tf32_rna(a0[j]);   // (r,   c)
                o.y = tf32_rna(a2[j]);   // (r+8, c)
                o.z = tf32_rna(a1[j]);   // (r,   c+4)
                o.w = tf32_rna(a3[j]);   // (r+8, c+4)
                dst[j] = o;
            }
        }
    }
}

// ---------- main kernel: BM128xBN128, 2 CTAs/SM, LDS.128 -> MMA --------------
__global__ void __launch_bounds__(NTH, 2)
moe_mma_kernel(const int*   __restrict__ offs_raw,
               const float* __restrict__ Bias,
               float*       __restrict__ Y)
{
    const int tid  = threadIdx.x;
    const int lane = tid & 31;
    const int wid  = tid >> 5;
    const int wm   = wid >> 1;   // 0..1
    const int wn   = wid & 1;    // 0..1
    const int n0   = blockIdx.x * BN;

    int e; long long row0; int rows;
    tile_scan(offs_raw, blockIdx.y, e, row0, rows);
    if (e < 0) return;

    extern __shared__ float smf[];
    const uint32_t smem_base = smem_u32(smf);

    const uint32_t* gA = g_Xr + (size_t)blockIdx.y * KCH * A_FLOATS;
    const uint32_t* gB = g_Wr + ((size_t)e * NT_TILES + blockIdx.x) * KCH * B_FLOATS;

    // prologue-only burst loader
    auto load_stage_burst = [&](int kc, int sidx) {
        const uint32_t ab = smem_base + (uint32_t)sidx * STAGE_B;
        const uint32_t bb = ab + A_FLOATS * 4;
        const uint32_t* ga = gA + (size_t)kc * A_FLOATS;
        const uint32_t* gb = gB + (size_t)kc * B_FLOATS;
        #pragma unroll
        for (int j = 0; j < 8; j++)
            cp16(ab + (uint32_t)(tid + j * 128) * 16u, ga + (size_t)(tid + j * 128) * 4);
        #pragma unroll
        for (int j = 0; j < 8; j++)
            cp16(bb + (uint32_t)(tid + j * 128) * 16u, gb + (size_t)(tid + j * 128) * 4);
        cp_commit();
    };

    float acc[4][8][4];
    #pragma unroll
    for (int mi = 0; mi < 4; mi++)
        #pragma unroll
        for (int nj = 0; nj < 8; nj++)
            #pragma unroll
            for (int q = 0; q < 4; q++) acc[mi][nj][q] = 0.0f;

    const uint32_t abw = (uint32_t)(wm * 32 + lane) * 16u;
    const uint32_t bbw = (uint32_t)(wn * 32 + lane) * 16u;

    load_stage_burst(0, 0);
    load_stage_burst(1, 1);

    uint32_t af[2][4][4], bq[2][4][4];

    int sidx = 0, pidx = 2;
    for (int kc = 0; kc < KCH; kc++) {
        cp_wait1();
        __syncthreads();

        const uint32_t As = smem_base + (uint32_t)sidx * STAGE_B;
        const uint32_t Bs = As + A_FLOATS * 4;

        auto load_frags = [&](int ks, int bi) {
            #pragma unroll
            for (int mi = 0; mi < 4; mi++)
                lds128(af[bi][mi], As + abw + (uint32_t)(ks * 4 + mi) * 1024u);
            #pragma unroll
            for (int njp = 0; njp < 4; njp++)
                lds128(bq[bi][njp], Bs + bbw + (uint32_t)(ks * 4 + njp) * 1024u);
        };

        // consumer work FIRST
        load_frags(0, 0);

        const bool pf = (kc + 2) < KCH;
        const uint32_t ab = smem_base + (uint32_t)pidx * STAGE_B;
        const uint32_t bb = ab + A_FLOATS * 4;
        const uint32_t* ga = gA + (size_t)(kc + 2) * A_FLOATS;
        const uint32_t* gb = gB + (size_t)(kc + 2) * B_FLOATS;

        #pragma unroll
        for (int ks = 0; ks < 4; ks++) {
            const int cur = ks & 1;
            if (ks < 3) load_frags(ks + 1, cur ^ 1);

            // scatter 4 of the 16 producer cp.async issues per ks
            if (pf) {
                #pragma unroll
                for (int j = 4 * ks; j < 4 * ks + 4; j++) {
                    if (j < 8) {
                        const uint32_t q = (uint32_t)(tid + j * 128);
                        cp16(ab + q * 16u, ga + (size_t)q * 4);
                    } else {
                        const uint32_t q = (uint32_t)(tid + (j - 8) * 128);
                        cp16(bb + q * 16u, gb + (size_t)q * 4);
                    }
                }
            }

            #pragma unroll
            for (int mi = 0; mi < 4; mi++) {
                #pragma unroll
                for (int njp = 0; njp < 4; njp++) {
                    mma8(acc[mi][2 * njp],     af[cur][mi], &bq[cur][njp][0]);
                    mma8(acc[mi][2 * njp + 1], af[cur][mi], &bq[cur][njp][2]);
                }
            }
        }
        cp_commit();   // one commit per kc -> wait1 semantics unchanged

        sidx = (sidx == STAGES - 1) ? 0 : sidx + 1;
        pidx = (pidx == STAGES - 1) ? 0 : pidx + 1;
    }

    // ---- epilogue: bias add + float2 stores ----
    const int lr = lane >> 2;
    const int lc = lane & 3;
    #pragma unroll
    for (int nj = 0; nj < 8; nj++) {
        const int gc = n0 + wn * 64 + nj * 8 + lc * 2;
        const float b0 = __ldg(Bias + (size_t)e * OUT_F + gc);
        const float b1 = __ldg(Bias + (size_t)e * OUT_F + gc + 1);
        #pragma unroll
        for (int mi = 0; mi < 4; mi++) {
            const int gr = wm * 64 + mi * 16 + lr;
            if (gr < rows) {
                float2 v;
                v.x = acc[mi][nj][0] + b0;
                v.y = acc[mi][nj][1] + b1;
                *(float2*)(Y + (size_t)(row0 + gr) * OUT_F + gc) = v;
            }
            if (gr + 8 < rows) {
                float2 v;
                v.x = acc[mi][nj][2] + b0;
                v.y = acc[mi][nj][3] + b1;
                *(float2*)(Y + (size_t)(row0 + gr + 8) * OUT_F + gc) = v;
            }
        }
    }
}

extern "C" void kernel_launch(void* const* d_in, const int* in_sizes, int n_in,
                              void* d_out, int out_size) {
    const float* X    = (const float*)d_in[0];
    const int*   offs = (const int*)d_in[1];
    const float* W    = (const float*)d_in[2];
    const float* Bias = (const float*)d_in[3];
    float*       Y    = (float*)d_out;

    pack_kernel<<<dim3(16, 128 + MAXMT), 256>>>(X, W, offs);

    cudaFuncSetAttribute(moe_mma_kernel,
                         cudaFuncAttributeMaxDynamicSharedMemorySize, SMEM_BYTES);
    dim3 grid(NT_TILES, MAXMT);
    moe_mma_kernel<<<grid, NTH, SMEM_BYTES>>>(offs, Bias, Y);
}